// round 5
// baseline (speedup 1.0000x reference)
#include <cuda_runtime.h>
#include <cstdint>

// CutOut restructured as: bulk cudaMemcpyAsync D2D (copy engine) of the whole
// 192MiB image tensor, then a tiny write-only fixup kernel that zeroes each
// image's clipped 50x50 window (<=1.9MB touched) and converts labels to float.
//
// images: (B=64, H=512, W=512, C=3) fp32.  Window per image: rows
// [ch-25, ch+25) ∩ [0,512), cols [cw-25, cw+25) ∩ [0,512); C innermost so the
// col range is 150 contiguous floats per row.

#define Bsz  64
#define Hsz  512
#define Wsz  512
#define Csz  3
#define HALF 25
#define LENW (2 * HALF)                 // 50
#define ROW_FLOATS   (Wsz * Csz)        // 1536
#define TOTAL_FLOATS (Bsz * Hsz * ROW_FLOATS)

__global__ __launch_bounds__(160)
void fixup_kernel(float* __restrict__ out,
                  const int* __restrict__ labels,
                  const int* __restrict__ center_h,
                  const int* __restrict__ center_w)
{
    const int b = blockIdx.x;           // image
    const int r = blockIdx.y;           // 0..49 window row index
    const int t = threadIdx.x;

    // Fused labels pass-through (int32 -> float32), once.
    if (b == 0 && r == 0 && t < Bsz) {
        out[TOTAL_FLOATS + t] = (float)__ldg(&labels[t]);
    }

    const int ch = __ldg(&center_h[b]);
    const int h  = ch - HALF + r;
    if (h < 0 || h >= Hsz) return;      // clipped at border

    const int cw   = __ldg(&center_w[b]);
    const int w_lo = max(cw - HALF, 0);
    const int w_hi = min(cw + HALF, Wsz);
    const int n    = (w_hi - w_lo) * Csz;   // <= 150 floats, contiguous
    if (t >= n) return;

    float* dst = out + ((long)b * Hsz + h) * ROW_FLOATS + w_lo * Csz;
    dst[t] = 0.0f;
}

extern "C" void kernel_launch(void* const* d_in, const int* in_sizes, int n_in,
                              void* d_out, int out_size)
{
    const float* images   = (const float*)d_in[0];
    const int*   labels   = (const int*)d_in[1];
    const int*   center_h = (const int*)d_in[2];
    const int*   center_w = (const int*)d_in[3];

    float* out = (float*)d_out;

    // Bulk copy of the whole image tensor on the capture (default) stream.
    cudaMemcpyAsync(out, images, (size_t)TOTAL_FLOATS * sizeof(float),
                    cudaMemcpyDeviceToDevice);

    // Zero the windows + labels, ordered after the copy (same stream).
    dim3 grid(Bsz, LENW);
    fixup_kernel<<<grid, 160>>>(out, labels, center_h, center_w);
}

// round 8
// speedup vs baseline: 1.0655x; 1.0655x over previous
#include <cuda_runtime.h>
#include <cstdint>

// CutOut: single fused kernel (memcpy+fixup route measured neutral-to-worse).
// images: (B=64, H=512, W=512, C=3) fp32.  Row = 1536 floats = 384 float4s.
// One 384-thread block handles 8 consecutive rows of one image (MLP=8,
// front-batched __ldcs loads, __stcs stores) -> grid = B*H/8 = 4096.
// Labels (int32 -> float32) fused into block 0.
// (Resubmission: previous round failed on container infra, not the kernel.)

#define Bsz  64
#define Hsz  512
#define Wsz  512
#define Csz  3
#define HALF 25
#define ROW_FLOATS   (Wsz * Csz)       // 1536
#define ROW_VEC4     (ROW_FLOATS / 4)  // 384
#define TOTAL_FLOATS (Bsz * Hsz * ROW_FLOATS)
#define ROWS_PER_BLK 8

__global__ __launch_bounds__(ROW_VEC4)
void cutout_kernel(const float4* __restrict__ in,
                   float4* __restrict__ out,
                   const int* __restrict__ labels,
                   const int* __restrict__ center_h,
                   const int* __restrict__ center_w)
{
    const int row0 = blockIdx.x * ROWS_PER_BLK;   // first global row
    const int b  = row0 >> 9;                     // / 512 (8 rows same image)
    const int h0 = row0 & (Hsz - 1);              // % 512

    const int t = threadIdx.x;
    const long base = (long)row0 * ROW_VEC4 + t;

    // Front-batched loads: 8 outstanding float4 loads per thread.
    float4 v[ROWS_PER_BLK];
#pragma unroll
    for (int r = 0; r < ROWS_PER_BLK; r++)
        v[r] = __ldcs(&in[base + (long)r * ROW_VEC4]);

    const int ch = __ldg(&center_h[b]);
    const int h_lo = ch - HALF, h_hi = ch + HALF;

    // Does any of our 8 rows intersect the vertical band?
    if (h0 + ROWS_PER_BLK > h_lo && h0 < h_hi) {
        const int cw = __ldg(&center_w[b]);
        const int w_lo = cw - HALF, w_hi = cw + HALF;
        const int e0 = t * 4;
        int w;
        w = e0 / 3;        const bool mx = (w >= w_lo) && (w < w_hi);
        w = (e0 + 1) / 3;  const bool my = (w >= w_lo) && (w < w_hi);
        w = (e0 + 2) / 3;  const bool mz = (w >= w_lo) && (w < w_hi);
        w = (e0 + 3) / 3;  const bool mw = (w >= w_lo) && (w < w_hi);

#pragma unroll
        for (int r = 0; r < ROWS_PER_BLK; r++) {
            if (h0 + r >= h_lo && h0 + r < h_hi) {
                if (mx) v[r].x = 0.f;
                if (my) v[r].y = 0.f;
                if (mz) v[r].z = 0.f;
                if (mw) v[r].w = 0.f;
            }
        }
    }

#pragma unroll
    for (int r = 0; r < ROWS_PER_BLK; r++)
        __stcs(&out[base + (long)r * ROW_VEC4], v[r]);

    // Fused labels pass-through (int32 -> float32), once, by block 0.
    if (blockIdx.x == 0 && t < Bsz) {
        float* tail = (float*)out + TOTAL_FLOATS;
        tail[t] = (float)__ldg(&labels[t]);
    }
}

extern "C" void kernel_launch(void* const* d_in, const int* in_sizes, int n_in,
                              void* d_out, int out_size)
{
    const float* images   = (const float*)d_in[0];
    const int*   labels   = (const int*)d_in[1];
    const int*   center_h = (const int*)d_in[2];
    const int*   center_w = (const int*)d_in[3];

    float* out = (float*)d_out;

    cutout_kernel<<<(Bsz * Hsz) / ROWS_PER_BLK, ROW_VEC4>>>(
        (const float4*)images, (float4*)out, labels, center_h, center_w);
}